// round 10
// baseline (speedup 1.0000x reference)
#include <cuda_runtime.h>

// BaseGraphPooling: segment-mean over sorted node_batch.
// node_h: [N,128] fp32, node_batch: [N] int32 sorted, out: [G,128] fp32.
//
// SINGLE kernel, per-graph finisher protocol, PRISTINE hot loop:
//  - 1184 CTAs, fixed contiguous row chunks (perfect per-SM byte balance).
//  - Hot loop identical to the best 2-kernel version: smem-staged indices,
//    smem bsearch for sub-segment bounds, red.global.add.v4 flushes. No
//    fences / signaling inside the loop.
//  - After the whole chunk: one __threadfence (cumulative, after
//    __syncthreads), then one ctrb signal per contributed graph.
//  - The unique CTA seeing a segment's END finishes it: computes exact
//    contributor count from chunk-edge peeks, spins until all arrive,
//    divides, writes out[g], zero-fills empty successors, re-zeros scratch
//    and counters (graph-replay safe). Epilogue overlaps other CTAs' streaming.

#define NUM_CTAS 1184       // 148 SMs * 8 CTAs/SM, one co-resident wave
#define MAX_G    1024
#define MAX_RPC  1728       // max rows_per_cta supported by smem staging
#define MAX_REC  64         // sub-segment records per CTA (data has ~2)

__device__ float4 g_scratch[MAX_G * 32];  // zero-init at load; finisher re-zeros
__device__ int    g_count[MAX_G];         // rows per graph (atomic)
__device__ int    g_ctrb[MAX_G];          // contributor arrivals per graph

__device__ __forceinline__ float4 f4add(float4 a, float4 b) {
    a.x += b.x; a.y += b.y; a.z += b.z; a.w += b.w; return a;
}

__device__ __forceinline__ void red_add_v4(float4* addr, float4 v) {
    asm volatile("red.global.add.v4.f32 [%0], {%1, %2, %3, %4};"
                 :: "l"(addr), "f"(v.x), "f"(v.y), "f"(v.z), "f"(v.w)
                 : "memory");
}

__device__ __forceinline__ void red_add_s32(int* addr, int v) {
    asm volatile("red.global.add.s32 [%0], %1;" :: "l"(addr), "r"(v) : "memory");
}

__global__ __launch_bounds__(256, 8)
void fused_segment_mean_kernel(const float4* __restrict__ h,    // N*32 float4
                               const int* __restrict__ batch,   // N int32, sorted
                               float4* __restrict__ out,        // G*32 float4
                               int N, int G, int rpc) {
    const int tid = threadIdx.x;
    const int c   = tid & 31;   // float4 column (0..31)
    const int r   = tid >> 5;   // row phase (0..7)
    const int bid = blockIdx.x;

    __shared__ float4 smem[256];
    __shared__ int    sb[MAX_RPC];
    __shared__ int    rec_g[MAX_REC];
    __shared__ unsigned char rec_end[MAX_REC], rec_first[MAX_REC];
    __shared__ int    rec_next[MAX_REC];
    __shared__ int    n_rec_s, cnt_s;

    if (tid == 0) n_rec_s = 0;

    const int c0 = bid * rpc;
    const int c1 = min(c0 + rpc, N);

    if (c0 < c1) {
        const int len = c1 - c0;
        for (int i = tid; i < len; i += 256)       // stage index slice
            sb[i] = batch[c0 + i];
        __syncthreads();

        if (bid == 0) {                            // empty prefix graphs
            const int first_id = sb[0];
            for (int z = tid; z < first_id * 32; z += 256)
                out[z] = make_float4(0.f, 0.f, 0.f, 0.f);
        }

        const int next_id = (c1 < N) ? batch[c1] : G;   // uniform L2 peek

        int s = c0;
        while (s < c1) {
            const int g = sb[s - c0];
            int lo = s, hi = c1;                  // upper_bound in smem
            while (lo < hi) {
                int mid = (lo + hi) >> 1;
                if (sb[mid - c0] <= g) lo = mid + 1; else hi = mid;
            }
            const int e = lo;

            float4 a0 = make_float4(0.f, 0.f, 0.f, 0.f);
            float4 a1 = a0, a2 = a0, a3 = a0;

            int i = s + r;
            for (; i + 24 < e; i += 32) {
                float4 v0 = __ldcs(&h[(size_t)(i     ) * 32 + c]);
                float4 v1 = __ldcs(&h[(size_t)(i +  8) * 32 + c]);
                float4 v2 = __ldcs(&h[(size_t)(i + 16) * 32 + c]);
                float4 v3 = __ldcs(&h[(size_t)(i + 24) * 32 + c]);
                a0 = f4add(a0, v0);
                a1 = f4add(a1, v1);
                a2 = f4add(a2, v2);
                a3 = f4add(a3, v3);
            }
            for (; i < e; i += 8)
                a0 = f4add(a0, __ldcs(&h[(size_t)i * 32 + c]));

            smem[tid] = f4add(f4add(a0, a1), f4add(a2, a3));
            __syncthreads();

            if (tid == 0) {
                red_add_s32(&g_count[g], e - s);
                int k = n_rec_s;                  // record this sub-segment
                if (k < MAX_REC) {
                    rec_g[k]     = g;
                    rec_end[k]   = (e < c1) || (next_id != g);
                    rec_first[k] = (s == c0);
                    rec_next[k]  = (e < c1) ? sb[e - c0] : next_id;
                    n_rec_s = k + 1;
                }
            }
            if (r == 0) {
                float4 acc = smem[c];
                #pragma unroll
                for (int p = 1; p < 8; p++)
                    acc = f4add(acc, smem[p * 32 + c]);
                red_add_v4(&g_scratch[(size_t)g * 32 + c], acc);
            }
            __syncthreads();                      // smem reuse safety
            s = e;
        }
    }
    __syncthreads();

    // ---- publish: one fence, one signal per contributed graph ----
    const int n_rec = n_rec_s;
    if (tid == 0) {
        __threadfence();                          // cumulative after barrier
        for (int k = 0; k < n_rec; k++)
            red_add_s32(&g_ctrb[rec_g[k]], 1);
    }

    // ---- finisher duties (overlap other CTAs' streaming) ----
    for (int k = 0; k < n_rec; k++) {
        if (!rec_end[k]) continue;
        const int g = rec_g[k];
        if (tid == 0) {
            int nc = 1;                           // self
            if (rec_first[k] && bid > 0) {        // contributors behind us
                int kk = bid - 1;
                while (kk >= 0 && batch[(size_t)(kk + 1) * rpc - 1] == g) {
                    nc++;
                    if (batch[(size_t)kk * rpc] != g) break;
                    kk--;
                }
            }
            while (atomicAdd(&g_ctrb[g], 0) < nc)
                __nanosleep(128);
            __threadfence();
            cnt_s = __ldcg(&g_count[g]);
        }
        __syncthreads();

        const float inv = 1.0f / (float)max(cnt_s, 1);

        if (tid < 32) {
            float4 v = __ldcg(&g_scratch[(size_t)g * 32 + tid]);
            g_scratch[(size_t)g * 32 + tid] = make_float4(0.f, 0.f, 0.f, 0.f);
            v.x *= inv; v.y *= inv; v.z *= inv; v.w *= inv;
            out[(size_t)g * 32 + tid] = v;
        } else if (tid == 32) {
            g_count[g] = 0;
            g_ctrb[g]  = 0;
        }

        const int nz = (rec_next[k] - g - 1) * 32;   // empty successor graphs
        for (int z = tid; z < nz; z += 256)
            out[(size_t)(g + 1) * 32 + z] = make_float4(0.f, 0.f, 0.f, 0.f);

        __syncthreads();
    }
}

extern "C" void kernel_launch(void* const* d_in, const int* in_sizes, int n_in,
                              void* d_out, int out_size) {
    const float4* h     = (const float4*)d_in[0];
    const int*    batch = (const int*)d_in[1];
    const int N = in_sizes[1];       // number of nodes
    const int G = out_size / 128;    // number of graphs

    int rpc = (N + NUM_CTAS - 1) / NUM_CTAS;   // <= MAX_RPC for this shape
    fused_segment_mean_kernel<<<NUM_CTAS, 256>>>(h, batch, (float4*)d_out,
                                                 N, G, rpc);
}

// round 11
// speedup vs baseline: 1.0027x; 1.0027x over previous
#include <cuda_runtime.h>

// BaseGraphPooling: segment-mean over sorted node_batch.
// node_h: [N,128] fp32, node_batch: [N] int32 sorted, out: [G,128] fp32.
//
// SINGLE kernel, per-graph finisher protocol, PRISTINE hot loop:
//  - 1184 CTAs, fixed contiguous row chunks (perfect per-SM byte balance).
//  - Hot loop identical to the best 2-kernel version: smem-staged indices,
//    smem bsearch for sub-segment bounds, red.global.add.v4 flushes. No
//    fences / signaling inside the loop.
//  - After the whole chunk: one __threadfence (cumulative, after
//    __syncthreads), then one ctrb signal per contributed graph.
//  - The unique CTA seeing a segment's END finishes it: computes exact
//    contributor count from chunk-edge peeks, spins until all arrive,
//    divides, writes out[g], zero-fills empty successors, re-zeros scratch
//    and counters (graph-replay safe). Epilogue overlaps other CTAs' streaming.

#define NUM_CTAS 1184       // 148 SMs * 8 CTAs/SM, one co-resident wave
#define MAX_G    1024
#define MAX_RPC  1728       // max rows_per_cta supported by smem staging
#define MAX_REC  64         // sub-segment records per CTA (data has ~2)

__device__ float4 g_scratch[MAX_G * 32];  // zero-init at load; finisher re-zeros
__device__ int    g_count[MAX_G];         // rows per graph (atomic)
__device__ int    g_ctrb[MAX_G];          // contributor arrivals per graph

__device__ __forceinline__ float4 f4add(float4 a, float4 b) {
    a.x += b.x; a.y += b.y; a.z += b.z; a.w += b.w; return a;
}

__device__ __forceinline__ void red_add_v4(float4* addr, float4 v) {
    asm volatile("red.global.add.v4.f32 [%0], {%1, %2, %3, %4};"
                 :: "l"(addr), "f"(v.x), "f"(v.y), "f"(v.z), "f"(v.w)
                 : "memory");
}

__device__ __forceinline__ void red_add_s32(int* addr, int v) {
    asm volatile("red.global.add.s32 [%0], %1;" :: "l"(addr), "r"(v) : "memory");
}

__global__ __launch_bounds__(256, 8)
void fused_segment_mean_kernel(const float4* __restrict__ h,    // N*32 float4
                               const int* __restrict__ batch,   // N int32, sorted
                               float4* __restrict__ out,        // G*32 float4
                               int N, int G, int rpc) {
    const int tid = threadIdx.x;
    const int c   = tid & 31;   // float4 column (0..31)
    const int r   = tid >> 5;   // row phase (0..7)
    const int bid = blockIdx.x;

    __shared__ float4 smem[256];
    __shared__ int    sb[MAX_RPC];
    __shared__ int    rec_g[MAX_REC];
    __shared__ unsigned char rec_end[MAX_REC], rec_first[MAX_REC];
    __shared__ int    rec_next[MAX_REC];
    __shared__ int    n_rec_s, cnt_s;

    if (tid == 0) n_rec_s = 0;

    const int c0 = bid * rpc;
    const int c1 = min(c0 + rpc, N);

    if (c0 < c1) {
        const int len = c1 - c0;
        for (int i = tid; i < len; i += 256)       // stage index slice
            sb[i] = batch[c0 + i];
        __syncthreads();

        if (bid == 0) {                            // empty prefix graphs
            const int first_id = sb[0];
            for (int z = tid; z < first_id * 32; z += 256)
                out[z] = make_float4(0.f, 0.f, 0.f, 0.f);
        }

        const int next_id = (c1 < N) ? batch[c1] : G;   // uniform L2 peek

        int s = c0;
        while (s < c1) {
            const int g = sb[s - c0];
            int lo = s, hi = c1;                  // upper_bound in smem
            while (lo < hi) {
                int mid = (lo + hi) >> 1;
                if (sb[mid - c0] <= g) lo = mid + 1; else hi = mid;
            }
            const int e = lo;

            float4 a0 = make_float4(0.f, 0.f, 0.f, 0.f);
            float4 a1 = a0, a2 = a0, a3 = a0;

            int i = s + r;
            for (; i + 24 < e; i += 32) {
                float4 v0 = __ldcs(&h[(size_t)(i     ) * 32 + c]);
                float4 v1 = __ldcs(&h[(size_t)(i +  8) * 32 + c]);
                float4 v2 = __ldcs(&h[(size_t)(i + 16) * 32 + c]);
                float4 v3 = __ldcs(&h[(size_t)(i + 24) * 32 + c]);
                a0 = f4add(a0, v0);
                a1 = f4add(a1, v1);
                a2 = f4add(a2, v2);
                a3 = f4add(a3, v3);
            }
            for (; i < e; i += 8)
                a0 = f4add(a0, __ldcs(&h[(size_t)i * 32 + c]));

            smem[tid] = f4add(f4add(a0, a1), f4add(a2, a3));
            __syncthreads();

            if (tid == 0) {
                red_add_s32(&g_count[g], e - s);
                int k = n_rec_s;                  // record this sub-segment
                if (k < MAX_REC) {
                    rec_g[k]     = g;
                    rec_end[k]   = (e < c1) || (next_id != g);
                    rec_first[k] = (s == c0);
                    rec_next[k]  = (e < c1) ? sb[e - c0] : next_id;
                    n_rec_s = k + 1;
                }
            }
            if (r == 0) {
                float4 acc = smem[c];
                #pragma unroll
                for (int p = 1; p < 8; p++)
                    acc = f4add(acc, smem[p * 32 + c]);
                red_add_v4(&g_scratch[(size_t)g * 32 + c], acc);
            }
            __syncthreads();                      // smem reuse safety
            s = e;
        }
    }
    __syncthreads();

    // ---- publish: one fence, one signal per contributed graph ----
    const int n_rec = n_rec_s;
    if (tid == 0) {
        __threadfence();                          // cumulative after barrier
        for (int k = 0; k < n_rec; k++)
            red_add_s32(&g_ctrb[rec_g[k]], 1);
    }

    // ---- finisher duties (overlap other CTAs' streaming) ----
    for (int k = 0; k < n_rec; k++) {
        if (!rec_end[k]) continue;
        const int g = rec_g[k];
        if (tid == 0) {
            int nc = 1;                           // self
            if (rec_first[k] && bid > 0) {        // contributors behind us
                int kk = bid - 1;
                while (kk >= 0 && batch[(size_t)(kk + 1) * rpc - 1] == g) {
                    nc++;
                    if (batch[(size_t)kk * rpc] != g) break;
                    kk--;
                }
            }
            while (atomicAdd(&g_ctrb[g], 0) < nc)
                __nanosleep(128);
            __threadfence();
            cnt_s = __ldcg(&g_count[g]);
        }
        __syncthreads();

        const float inv = 1.0f / (float)max(cnt_s, 1);

        if (tid < 32) {
            float4 v = __ldcg(&g_scratch[(size_t)g * 32 + tid]);
            g_scratch[(size_t)g * 32 + tid] = make_float4(0.f, 0.f, 0.f, 0.f);
            v.x *= inv; v.y *= inv; v.z *= inv; v.w *= inv;
            out[(size_t)g * 32 + tid] = v;
        } else if (tid == 32) {
            g_count[g] = 0;
            g_ctrb[g]  = 0;
        }

        const int nz = (rec_next[k] - g - 1) * 32;   // empty successor graphs
        for (int z = tid; z < nz; z += 256)
            out[(size_t)(g + 1) * 32 + z] = make_float4(0.f, 0.f, 0.f, 0.f);

        __syncthreads();
    }
}

extern "C" void kernel_launch(void* const* d_in, const int* in_sizes, int n_in,
                              void* d_out, int out_size) {
    const float4* h     = (const float4*)d_in[0];
    const int*    batch = (const int*)d_in[1];
    const int N = in_sizes[1];       // number of nodes
    const int G = out_size / 128;    // number of graphs

    int rpc = (N + NUM_CTAS - 1) / NUM_CTAS;   // <= MAX_RPC for this shape
    fused_segment_mean_kernel<<<NUM_CTAS, 256>>>(h, batch, (float4*)d_out,
                                                 N, G, rpc);
}

// round 12
// speedup vs baseline: 1.0282x; 1.0255x over previous
#include <cuda_runtime.h>

// BaseGraphPooling: segment-mean over sorted node_batch.
// node_h: [N,128] fp32, node_batch: [N] int32 sorted, out: [G,128] fp32.
//
// 2 launches (PDL-chained), self-cleaning device scratch:
//  1) chunk_sum : 1184 persistent-ish CTAs DYNAMICALLY grab 212-row chunks
//                 via a global ticket (work stealing kills the slow-SM
//                 straggler tail that static 1690-row chunks exposed).
//                 Per chunk: stage indices to smem, smem bsearch for
//                 sub-segment bounds, 4x-unrolled float4 streaming,
//                 red.global.add.v4 into g_scratch + length into g_count.
//  2) divide    : griddepsync (primary grid fully done), then per-(g,c)
//                 scale by 1/max(count,1), write d_out, re-zero scratch,
//                 counters, and the ticket for the next graph replay.

#define NUM_CTAS 1184       // 148 SMs * 8 CTAs/SM, one co-resident wave
#define MAX_G    1024
#define RPC      212        // rows per chunk (fine grain for work stealing)

__device__ float4       g_scratch[MAX_G * 32];  // zero-init; divide re-zeros
__device__ int          g_count[MAX_G];         // rows per graph
__device__ unsigned int g_ticket = 0;           // chunk dispenser

__device__ __forceinline__ float4 f4add(float4 a, float4 b) {
    a.x += b.x; a.y += b.y; a.z += b.z; a.w += b.w; return a;
}

__device__ __forceinline__ void red_add_v4(float4* addr, float4 v) {
    asm volatile("red.global.add.v4.f32 [%0], {%1, %2, %3, %4};"
                 :: "l"(addr), "f"(v.x), "f"(v.y), "f"(v.z), "f"(v.w)
                 : "memory");
}

__device__ __forceinline__ void red_add_s32(int* addr, int v) {
    asm volatile("red.global.add.s32 [%0], %1;" :: "l"(addr), "r"(v) : "memory");
}

__global__ __launch_bounds__(256, 8)
void chunk_sum_kernel(const float4* __restrict__ h,    // N*32 float4
                      const int* __restrict__ batch,   // N int32, sorted
                      int N, int nchunk) {
    const int tid = threadIdx.x;
    const int c   = tid & 31;   // float4 column (0..31)
    const int r   = tid >> 5;   // row phase (0..7)

    __shared__ float4       smem[256];
    __shared__ int          sb[RPC];
    __shared__ unsigned int tkt_s;

    for (;;) {
        // ---- grab next chunk ----
        if (tid == 0)
            tkt_s = atomicAdd(&g_ticket, 1u);
        __syncthreads();
        const unsigned int t = tkt_s;
        __syncthreads();                 // tkt_s reusable next iteration
        if (t >= (unsigned)nchunk) return;

        const int c0 = (int)t * RPC;
        const int c1 = min(c0 + RPC, N);
        const int len = c1 - c0;

        // Stage this chunk's index slice into smem (one coalesced burst).
        if (tid < len)
            sb[tid] = batch[c0 + tid];
        __syncthreads();

        int s = c0;
        while (s < c1) {
            const int g = sb[s - c0];           // current segment id (uniform)
            int lo = s, hi = c1;                // upper_bound via smem bsearch
            while (lo < hi) {
                int mid = (lo + hi) >> 1;
                if (sb[mid - c0] <= g) lo = mid + 1; else hi = mid;
            }
            const int e = lo;

            float4 a0 = make_float4(0.f, 0.f, 0.f, 0.f);
            float4 a1 = a0, a2 = a0, a3 = a0;

            int i = s + r;
            for (; i + 24 < e; i += 32) {
                float4 v0 = __ldcs(&h[(size_t)(i     ) * 32 + c]);
                float4 v1 = __ldcs(&h[(size_t)(i +  8) * 32 + c]);
                float4 v2 = __ldcs(&h[(size_t)(i + 16) * 32 + c]);
                float4 v3 = __ldcs(&h[(size_t)(i + 24) * 32 + c]);
                a0 = f4add(a0, v0);
                a1 = f4add(a1, v1);
                a2 = f4add(a2, v2);
                a3 = f4add(a3, v3);
            }
            for (; i < e; i += 8)
                a0 = f4add(a0, __ldcs(&h[(size_t)i * 32 + c]));

            smem[tid] = f4add(f4add(a0, a1), f4add(a2, a3));
            __syncthreads();

            if (tid == 0)
                red_add_s32(&g_count[g], e - s);
            if (r == 0) {
                float4 acc = smem[c];
                #pragma unroll
                for (int p = 1; p < 8; p++)
                    acc = f4add(acc, smem[p * 32 + c]);
                red_add_v4(&g_scratch[(size_t)g * 32 + c], acc);
            }
            __syncthreads();                    // smem reuse safety
            s = e;
        }
    }
}

__global__ void divide_kernel(float4* __restrict__ out, int G) {
    const int idx = blockIdx.x * blockDim.x + threadIdx.x;
    const int g = idx >> 5;
    const int c = idx & 31;

    cudaGridDependencySynchronize();   // primary grid fully complete

    if (idx == 0) g_ticket = 0;        // safe: no chunk_sum thread running

    if (g >= G) return;

    const int cnt = g_count[g];
    const float inv = 1.0f / (float)max(cnt, 1);

    float4 v = g_scratch[(size_t)g * 32 + c];
    // Self-cleaning for the next graph replay.
    g_scratch[(size_t)g * 32 + c] = make_float4(0.f, 0.f, 0.f, 0.f);
    if (c == 0) g_count[g] = 0;

    v.x *= inv; v.y *= inv; v.z *= inv; v.w *= inv;
    out[(size_t)g * 32 + c] = v;
}

extern "C" void kernel_launch(void* const* d_in, const int* in_sizes, int n_in,
                              void* d_out, int out_size) {
    const float4* h     = (const float4*)d_in[0];
    const int*    batch = (const int*)d_in[1];
    const int N = in_sizes[1];       // number of nodes
    const int G = out_size / 128;    // number of graphs

    const int nchunk = (N + RPC - 1) / RPC;
    chunk_sum_kernel<<<NUM_CTAS, 256>>>(h, batch, N, nchunk);

    cudaLaunchAttribute pdl[1];
    pdl[0].id = cudaLaunchAttributeProgrammaticStreamSerialization;
    pdl[0].val.programmaticStreamSerializationAllowed = 1;

    cudaLaunchConfig_t cfg = {};
    cfg.gridDim  = dim3((G * 32 + 255) / 256, 1, 1);
    cfg.blockDim = dim3(256, 1, 1);
    cfg.stream   = 0;
    cfg.attrs    = pdl;
    cfg.numAttrs = 1;
    cudaLaunchKernelEx(&cfg, divide_kernel, (float4*)d_out, G);
}